// round 12
// baseline (speedup 1.0000x reference)
#include <cuda_runtime.h>

// Online Normalization forward, fused persistent kernel (v12 = v11 + pure phases).
// x: [B=32, H=64, W=64, C=256] channels-last, fp32.
//
// 128 CTAs x 1024 threads (1/SM, co-resident -> grid barrier safe).
// 2 super-stages of 16 batches (67 MB each; fits L2). Every DRAM phase is
// isolated by a grid barrier so read and write streams never mix:
//   stats(0) |B| scan+norm(0) |B| stats(1) |B| scan+norm(1)
// Norm re-reads the chunk this CTA just streamed (tail in L1, rest in L2),
// so DRAM sees only the 134 MB input read + 134 MB output write.

#define AFWD 0.999f
#define EPS  1e-5f

constexpr int Bn   = 32;
constexpr int HW   = 64 * 64;      // 4096 rows per batch
constexpr int Cc   = 256;
constexpr int C4   = Cc / 4;       // 64
constexpr int NCTA = 128;
constexpr int TPB  = 1024;
constexpr int NSTG = 2;
constexpr int GB   = Bn / NSTG;    // 16 batches per stage
constexpr int CPB  = NCTA / GB;    // 8 CTAs per batch
constexpr int ROWS = HW / CPB;     // 512 rows per CTA per stage
constexpr int RG   = TPB / C4;     // 16 row groups
constexpr int ITER = ROWS / RG;    // 32 rows per thread per stage

__device__ float g_ps[NSTG][NCTA * Cc];   // per-chunk partials, stage-buffered
__device__ float g_pq[NSTG][NCTA * Cc];
__device__ unsigned long long g_bar;      // monotonic across graph replays

// Dynamic smem (floats):
//   [0 : 8192)    union: reduce (red_s 0:4096, red_q 4096:8192)
//                        staging (st_s 0:4096, st_q 4096:8192)
//   [8192 : 12288)  sm_mu [16 x 256]
//   [12288: 16384)  sm_rs [16 x 256]
constexpr int SMEM_FLOATS = 16384;        // 64 KB -> big L1D carveout

__device__ __forceinline__ void grid_barrier() {
    __syncthreads();
    if (threadIdx.x == 0) {
        __threadfence();
        unsigned long long t = atomicAdd(&g_bar, 1ULL) + 1ULL;
        unsigned long long target = ((t + NCTA - 1ULL) / NCTA) * NCTA;
        while (*((volatile unsigned long long*)&g_bar) < target) { }
        __threadfence();
    }
    __syncthreads();
}

__global__ __launch_bounds__(TPB, 1)
void onorm_fused(const float4* __restrict__ x4,
                 float4* __restrict__ o4,
                 const float* __restrict__ mu0,
                 const float* __restrict__ var0) {
    extern __shared__ float sm[];
    float* red_s = sm;                 // 4096 floats
    float* red_q = sm + 4096;          // 4096 floats
    float* st_s  = sm;                 // 4096 floats (after barrier)
    float* st_q  = sm + 4096;          // 4096 floats
    float* sm_mu = sm + 8192;          // 4096 floats
    float* sm_rs = sm + 12288;         // 4096 floats

    const int tid = threadIdx.x;
    const int cta = blockIdx.x;
    const int c4  = tid & 63;          // float4 channel index
    const int rg  = tid >> 6;          // 0..15 row group
    const int bl  = cta >> 3;          // local batch index (0..15)
    const int s   = cta & 7;           // chunk within the batch

    // EMA state carried across stages in registers of threads 0..255
    float mu = 0.f, var = 1.f;
    if (tid < Cc) { mu = mu0[tid]; var = var0[tid]; }

    #pragma unroll
    for (int g = 0; g < NSTG; g++) {
        const int t = g * GB + bl;     // global batch this CTA handles
        const size_t base = ((size_t)t * HW + (size_t)s * ROWS + rg) * C4 + c4;
        const float4* p = x4 + base;

        // ---------- stats: pure read stream, static loop ----------
        float4 a = {0.f,0.f,0.f,0.f}, q = {0.f,0.f,0.f,0.f};
        #pragma unroll 8
        for (int i = 0; i < ITER; i++) {
            float4 v = p[(size_t)i * RG * C4];
            a.x += v.x; a.y += v.y; a.z += v.z; a.w += v.w;
            q.x = fmaf(v.x, v.x, q.x); q.y = fmaf(v.y, v.y, q.y);
            q.z = fmaf(v.z, v.z, q.z); q.w = fmaf(v.w, v.w, q.w);
        }
        ((float4*)red_s)[rg * 64 + c4] = a;
        ((float4*)red_q)[rg * 64 + c4] = q;
        __syncthreads();
        if (tid < 64) {
            float4 sa = {0.f,0.f,0.f,0.f}, sq = {0.f,0.f,0.f,0.f};
            #pragma unroll
            for (int j = 0; j < RG; j++) {
                float4 va = ((float4*)red_s)[j * 64 + tid];
                float4 vq = ((float4*)red_q)[j * 64 + tid];
                sa.x += va.x; sa.y += va.y; sa.z += va.z; sa.w += va.w;
                sq.x += vq.x; sq.y += vq.y; sq.z += vq.z; sq.w += vq.w;
            }
            ((float4*)g_ps[g])[cta * 64 + tid] = sa;
            ((float4*)g_pq[g])[cta * 64 + tid] = sq;
        }

        grid_barrier();   // all stats of stage g visible; read phase ends

        // ---------- fold 8 chunk-partials per batch into smem ----------
        for (int i = tid; i < GB * Cc; i += TPB) {
            const int b = ((i >> 8) << 3) * Cc + (i & 255);   // (bb*8)*Cc + c
            float ss = 0.f, qq = 0.f;
            #pragma unroll
            for (int k = 0; k < CPB; k++) {
                ss += g_ps[g][b + k * Cc];
                qq += g_pq[g][b + k * Cc];
            }
            st_s[i] = ss;
            st_q[i] = qq;
        }
        __syncthreads();

        // ---------- 16-step EMA scan (register state) into smem mu/rs ----------
        if (tid < Cc) {
            const float inv = 1.0f / (float)HW;
            #pragma unroll
            for (int b = 0; b < GB; b++) {
                sm_mu[b * Cc + tid] = mu;
                sm_rs[b * Cc + tid] = rsqrtf(var + EPS);
                const float mean = st_s[b * Cc + tid] * inv;
                const float vart = fmaf(-mean, mean, st_q[b * Cc + tid] * inv);
                const float d    = mean - mu;
                var = AFWD * var + (1.0f - AFWD) * vart
                    + AFWD * (1.0f - AFWD) * d * d;
                mu  = fmaf(1.0f - AFWD, d, mu);
            }
        }
        __syncthreads();

        // ---------- normalize: write-dominated phase, reverse order ----------
        // Plain loads: chunk tail in L1, remainder L2-resident (67 MB stage
        // window). Streaming stores keep output from evicting x.
        const float4 m = ((const float4*)sm_mu)[bl * 64 + c4];
        const float4 r = ((const float4*)sm_rs)[bl * 64 + c4];
        float4* o = o4 + base;
        #pragma unroll 8
        for (int i = ITER - 1; i >= 0; i--) {
            float4 v = p[(size_t)i * RG * C4];
            float4 w;
            w.x = (v.x - m.x) * r.x;
            w.y = (v.y - m.y) * r.y;
            w.z = (v.z - m.z) * r.z;
            w.w = (v.w - m.w) * r.w;
            __stcs(&o[(size_t)i * RG * C4], w);
        }

        // Isolate the write phase from next stage's read phase (the v11 bug).
        if (g + 1 < NSTG) grid_barrier();
    }
}

extern "C" void kernel_launch(void* const* d_in, const int* in_sizes, int n_in,
                              void* d_out, int out_size) {
    const float* x    = (const float*)d_in[0];
    const float* mu0  = (const float*)d_in[1];
    const float* var0 = (const float*)d_in[2];
    float* out = (float*)d_out;

    static bool attr_set = false;
    if (!attr_set) {
        cudaFuncSetAttribute(onorm_fused,
                             cudaFuncAttributeMaxDynamicSharedMemorySize,
                             SMEM_FLOATS * sizeof(float));
        attr_set = true;
    }

    onorm_fused<<<NCTA, TPB, SMEM_FLOATS * sizeof(float)>>>(
        (const float4*)x, (float4*)out, mu0, var0);
}